// round 3
// baseline (speedup 1.0000x reference)
#include <cuda_runtime.h>

#define NN 50000
#define NE 800000
#define DD 128

// ---------------- scratch (static device globals; no allocation) ----------------
__device__ int   g_is64;             // 1 if edge_index is int64, 0 if int32
__device__ int   g_deg[NN];
__device__ int   g_off[NN + 1];
__device__ int   g_cur[NN];
__device__ float g_invdeg[NN];
__device__ int   g_col[NE];
__device__ float g_agg[(size_t)NN * DD];
__device__ float g_h1 [(size_t)NN * DD];
__device__ float g_h2 [(size_t)NN * DD];

// Buffer selector: 0 -> external x, 1 -> g_h1, 2 -> g_h2 (resolved on device)
__device__ __forceinline__ const float* sel_in(int sel, const float* x) {
    return sel == 0 ? x : (sel == 1 ? (const float*)g_h1 : (const float*)g_h2);
}

// Edge accessors valid for either dtype layout (ei viewed as int32 words).
__device__ __forceinline__ int get_src(const int* __restrict__ ei, int e) {
    return g_is64 ? ei[2 * e] : ei[e];
}
__device__ __forceinline__ int get_dst(const int* __restrict__ ei, int e) {
    return g_is64 ? ei[2 * NE + 2 * e] : ei[NE + e];
}

// ---------------- dtype detection ----------------
// If edge_index is int64 (values < 50000), every odd 32-bit word of the first
// 512 words is a zero high-word. If int32, those are random node ids.
__global__ void k_detect(const int* __restrict__ ei) {
    if (threadIdx.x == 0 && blockIdx.x == 0) {
        int acc = 0;
        for (int i = 1; i < 512; i += 2) acc |= ei[i];
        g_is64 = (acc == 0) ? 1 : 0;
    }
}

// ---------------- CSR build ----------------
__global__ void k_zero_deg() {
    int i = blockIdx.x * blockDim.x + threadIdx.x;
    if (i < NN) g_deg[i] = 0;
}

__global__ void k_hist(const int* __restrict__ ei) {
    int e = blockIdx.x * blockDim.x + threadIdx.x;
    if (e < NE) {
        int d = get_dst(ei, e);
        if ((unsigned)d < NN) atomicAdd(&g_deg[d], 1);
    }
}

// Single-block exclusive scan over g_deg -> g_off/g_cur, plus inv-degree.
__global__ void k_scan() {
    __shared__ int s[1024];
    const int t = threadIdx.x;
    const int CH = (NN + 1023) / 1024;   // 49
    int beg = t * CH;
    int end = beg + CH; if (end > NN) end = NN;
    if (beg > NN) beg = NN;

    int sum = 0;
    for (int i = beg; i < end; ++i) sum += g_deg[i];
    s[t] = sum;
    __syncthreads();
    for (int d = 1; d < 1024; d <<= 1) {
        int v = (t >= d) ? s[t - d] : 0;
        __syncthreads();
        if (t >= d) s[t] += v;
        __syncthreads();
    }
    int run = (t == 0) ? 0 : s[t - 1];
    for (int i = beg; i < end; ++i) {
        g_off[i] = run;
        g_cur[i] = run;
        int dg = g_deg[i];
        g_invdeg[i] = 1.0f / (float)(dg > 0 ? dg : 1);
        run += dg;
    }
    if (t == 1023) g_off[NN] = s[1023];
}

__global__ void k_fill(const int* __restrict__ ei) {
    int e = blockIdx.x * blockDim.x + threadIdx.x;
    if (e < NE) {
        int d = get_dst(ei, e);
        int s = get_src(ei, e);
        if ((unsigned)d < NN && (unsigned)s < NN) {
            int p = atomicAdd(&g_cur[d], 1);
            g_col[p] = s;
        }
    }
}

// ---------------- mean aggregation: one warp per node ----------------
__global__ __launch_bounds__(256) void k_agg(int sel, const float* __restrict__ x) {
    int node = (blockIdx.x * blockDim.x + threadIdx.x) >> 5;
    int lane = threadIdx.x & 31;
    if (node >= NN) return;

    const float* h = sel_in(sel, x);

    int beg = g_off[node];
    int end = g_off[node + 1];

    float ax = 0.f, ay = 0.f, az = 0.f, aw = 0.f;
    for (int e = beg; e < end; ++e) {
        int s = g_col[e];
        float4 v = *(((const float4*)(h + (size_t)s * DD)) + lane);
        ax += v.x; ay += v.y; az += v.z; aw += v.w;
    }
    float inv = g_invdeg[node];
    float4 o = make_float4(ax * inv, ay * inv, az * inv, aw * inv);
    ((float4*)(g_agg + (size_t)node * DD))[lane] = o;
}

// ---------------- fused GEMM: out = agg @ Wl^T + h @ Wr^T + b (+relu) ----------
// Logical A = [agg | h]  (M x 256),  B[k][o] = Wl[o][k] (k<128) else Wr[o][k-128]
// BM=64, BN=128, BK=32, 256 threads, 8x4 register tile per thread.
__global__ __launch_bounds__(256) void k_gemm(int in_sel, const float* __restrict__ x,
                                              const float* __restrict__ Wl,
                                              const float* __restrict__ bl,
                                              const float* __restrict__ Wr,
                                              int out_sel, float* __restrict__ ext_out,
                                              int relu) {
    __shared__ float As[32][64];
    __shared__ float Bs[32][128];

    const float* A0 = (const float*)g_agg;      // aggregated features
    const float* A1 = sel_in(in_sel, x);        // node's own features
    float* out = out_sel == 0 ? ext_out : (out_sel == 1 ? (float*)g_h1 : (float*)g_h2);

    const int tid = threadIdx.x;
    const int tx  = tid & 31;   // output-dim group (o = tx*4 .. tx*4+3)
    const int ty  = tid >> 5;   // row group (rows ty*8 .. ty*8+7)
    const int blockM = blockIdx.x * 64;

    float acc[8][4];
#pragma unroll
    for (int i = 0; i < 8; ++i)
#pragma unroll
        for (int j = 0; j < 4; ++j) acc[i][j] = 0.f;

    const int lr = tid >> 3;         // 0..31, A-tile row within half
    const int lk = (tid & 7) << 2;   // 0,4,...,28

    for (int kc = 0; kc < 256; kc += 32) {
        const float* A = (kc < 128) ? A0 : A1;
        const float* W = (kc < 128) ? Wl : Wr;
        const int kb = kc & 127;

        // A tile: 64 rows x 32 k, stored transposed As[k][m]
#pragma unroll
        for (int rr = 0; rr < 64; rr += 32) {
            int row = blockM + lr + rr;
            float4 v = make_float4(0.f, 0.f, 0.f, 0.f);
            if (row < NN)
                v = *(const float4*)(A + (size_t)row * DD + kb + lk);
            As[lk + 0][lr + rr] = v.x;
            As[lk + 1][lr + rr] = v.y;
            As[lk + 2][lr + rr] = v.z;
            As[lk + 3][lr + rr] = v.w;
        }
        // B tile: Bs[k][o] = W[o][kb+k]; 128 o x 32 k
#pragma unroll
        for (int it = 0; it < 4; ++it) {
            int idx = tid + it * 256;       // 0..1023
            int o   = idx >> 3;             // 0..127
            int k4  = (idx & 7) << 2;       // 0..28
            float4 v = *(const float4*)(W + o * DD + kb + k4);
            Bs[k4 + 0][o] = v.x;
            Bs[k4 + 1][o] = v.y;
            Bs[k4 + 2][o] = v.z;
            Bs[k4 + 3][o] = v.w;
        }
        __syncthreads();

#pragma unroll
        for (int k = 0; k < 32; ++k) {
            float4 a0 = *(const float4*)&As[k][ty * 8];
            float4 a1 = *(const float4*)&As[k][ty * 8 + 4];
            float4 b  = *(const float4*)&Bs[k][tx * 4];
            float a[8] = {a0.x, a0.y, a0.z, a0.w, a1.x, a1.y, a1.z, a1.w};
#pragma unroll
            for (int i = 0; i < 8; ++i) {
                acc[i][0] += a[i] * b.x;
                acc[i][1] += a[i] * b.y;
                acc[i][2] += a[i] * b.z;
                acc[i][3] += a[i] * b.w;
            }
        }
        __syncthreads();
    }

    float4 bb = *(const float4*)(bl + tx * 4);
#pragma unroll
    for (int i = 0; i < 8; ++i) {
        int row = blockM + ty * 8 + i;
        if (row < NN) {
            float4 o;
            o.x = acc[i][0] + bb.x;
            o.y = acc[i][1] + bb.y;
            o.z = acc[i][2] + bb.z;
            o.w = acc[i][3] + bb.w;
            if (relu) {
                o.x = fmaxf(o.x, 0.f); o.y = fmaxf(o.y, 0.f);
                o.z = fmaxf(o.z, 0.f); o.w = fmaxf(o.w, 0.f);
            }
            *(float4*)(out + (size_t)row * DD + tx * 4) = o;
        }
    }
}

// ---------------- launch (kernel launches ONLY; graph-capture safe) ----------
extern "C" void kernel_launch(void* const* d_in, const int* in_sizes, int n_in,
                              void* d_out, int out_size) {
    const float* x  = (const float*)d_in[0];
    const int*   ei = (const int*)d_in[1];   // int32 words (handles int64 too via g_is64)
    const float* Wl1 = (const float*)d_in[2];
    const float* bl1 = (const float*)d_in[3];
    const float* Wr1 = (const float*)d_in[4];
    const float* Wl2 = (const float*)d_in[5];
    const float* bl2 = (const float*)d_in[6];
    const float* Wr2 = (const float*)d_in[7];
    const float* Wl3 = (const float*)d_in[8];
    const float* bl3 = (const float*)d_in[9];
    const float* Wr3 = (const float*)d_in[10];
    float* out = (float*)d_out;

    // CSR build (reused across all 3 layers)
    k_detect<<<1, 32>>>(ei);
    k_zero_deg<<<(NN + 255) / 256, 256>>>();
    k_hist<<<(NE + 255) / 256, 256>>>(ei);
    k_scan<<<1, 1024>>>();
    k_fill<<<(NE + 255) / 256, 256>>>(ei);

    const int aggGrid  = (NN + 7) / 8;     // 8 warps (nodes) per 256-thread block
    const int gemmGrid = (NN + 63) / 64;

    // Layer 1 (+ReLU): agg(x) -> g_agg; gemm -> g_h1
    k_agg<<<aggGrid, 256>>>(0, x);
    k_gemm<<<gemmGrid, 256>>>(0, x, Wl1, bl1, Wr1, 1, out, 1);
    // Layer 2: agg(g_h1) -> g_agg; gemm -> g_h2
    k_agg<<<aggGrid, 256>>>(1, x);
    k_gemm<<<gemmGrid, 256>>>(1, x, Wl2, bl2, Wr2, 2, out, 0);
    // Layer 3: agg(g_h2) -> g_agg; gemm -> d_out
    k_agg<<<aggGrid, 256>>>(2, x);
    k_gemm<<<gemmGrid, 256>>>(2, x, Wl3, bl3, Wr3, 0, out, 0);
}